// round 6
// baseline (speedup 1.0000x reference)
#include <cuda_runtime.h>
#include <cstddef>

// Problem constants
#define BATCH   16
#define IN_CH   2
#define FDIM    2048
#define TDIM    1024
#define NBANDS  64
#define BANDSZ  32      // FDIM / NBANDS
#define EMB     128

#define T_CHUNK 256
#define THREADS 256

__global__ __launch_bounds__(THREADS, 8)
void bandsplit_kernel(const float* __restrict__ x,
                      const float* __restrict__ W,
                      const float* __restrict__ bias,
                      float* __restrict__ out)
{
    // Single 8 KB buffer: phase-1 partials [ch][fgroup][t4col], then reused
    // as the final means via in-place reduction into fg=0.
    __shared__ float4 part[IN_CH][4][T_CHUNK / 4];

    const int g  = blockIdx.x;
    const int tc = g & 3;               // t-chunk index (TDIM / T_CHUNK = 4)
    const int n  = (g >> 2) & 63;       // band
    const int b  = g >> 8;              // batch
    const int t0 = tc * T_CHUNK;
    const int tid = threadIdx.x;

    // ---------------- Phase 1: band sum, float4, 4-way f-split --------------
    const int t4 = tid & 63;            // float4 column (64 cols = 256 t)
    const int fg = tid >> 6;            // f-group: 8 rows each

    const size_t ft   = (size_t)FDIM * TDIM;
    const int    row4 = TDIM / 4;

    const float4* xp0 = (const float4*)(x + (size_t)b * IN_CH * ft
                                          + (size_t)(n * BANDSZ + fg * 8) * TDIM
                                          + t0) + t4;
    const float4* xp1 = xp0 + ft / 4;

    float4 s0 = make_float4(0.f, 0.f, 0.f, 0.f);
    float4 s1 = make_float4(0.f, 0.f, 0.f, 0.f);
    #pragma unroll
    for (int f = 0; f < 8; f++) {
        const float4 v = __ldcs(xp0 + (size_t)f * row4);
        s0.x += v.x; s0.y += v.y; s0.z += v.z; s0.w += v.w;
    }
    #pragma unroll
    for (int f = 0; f < 8; f++) {
        const float4 v = __ldcs(xp1 + (size_t)f * row4);
        s1.x += v.x; s1.y += v.y; s1.z += v.z; s1.w += v.w;
    }
    part[0][fg][t4] = s0;
    part[1][fg][t4] = s1;
    __syncthreads();

    // Cross-f reduction into part[c][0][*], scaled to the mean.
    if (tid < 128) {
        const int c   = tid >> 6;
        const int tc4 = tid & 63;
        const float4 p0 = part[c][0][tc4];
        const float4 p1 = part[c][1][tc4];
        const float4 p2 = part[c][2][tc4];
        const float4 p3 = part[c][3][tc4];
        const float inv = 1.f / BANDSZ;
        float4 m;
        m.x = (p0.x + p1.x + p2.x + p3.x) * inv;
        m.y = (p0.y + p1.y + p2.y + p3.y) * inv;
        m.z = (p0.z + p1.z + p2.z + p3.z) * inv;
        m.w = (p0.w + p1.w + p2.w + p3.w) * inv;
        part[c][0][tc4] = m;
    }

    // Load weights (independent of smem traffic above).
    const int e4   = (tid & 31) * 4;
    const int trow = tid >> 5;

    const float4 w0 = *(const float4*)(W + ((size_t)n * IN_CH + 0) * EMB + e4);
    const float4 w1 = *(const float4*)(W + ((size_t)n * IN_CH + 1) * EMB + e4);
    const float4 bb = *(const float4*)(bias + (size_t)n * EMB + e4);

    __syncthreads();

    // ---------------- Phase 2: project to EMB and write ---------------------
    const float* xm0 = (const float*)&part[0][0][0];   // 256 means, ch 0
    const float* xm1 = (const float*)&part[1][0][0];   // 256 means, ch 1

    // out index: ((b*NBANDS + n)*TDIM + t)*EMB + e
    float4* op = (float4*)(out + (((size_t)b * NBANDS + n) * TDIM + t0) * EMB + e4);

    #pragma unroll 8
    for (int i = 0; i < T_CHUNK / 8; i++) {
        const int t = trow + i * 8;
        const float m0 = xm0[t];        // warp-uniform smem broadcast
        const float m1 = xm1[t];
        float4 r;
        r.x = fmaf(m0, w0.x, fmaf(m1, w1.x, bb.x));
        r.y = fmaf(m0, w0.y, fmaf(m1, w1.y, bb.y));
        r.z = fmaf(m0, w0.z, fmaf(m1, w1.z, bb.z));
        r.w = fmaf(m0, w0.w, fmaf(m1, w1.w, bb.w));
        __stcs(op + (size_t)t * (EMB / 4), r);
    }
}

extern "C" void kernel_launch(void* const* d_in, const int* in_sizes, int n_in,
                              void* d_out, int out_size)
{
    const float* x    = (const float*)d_in[0];
    const float* W    = (const float*)d_in[1];
    const float* bias = (const float*)d_in[2];
    float* out        = (float*)d_out;

    const int grid = BATCH * NBANDS * (TDIM / T_CHUNK);  // 4096
    bandsplit_kernel<<<grid, THREADS>>>(x, W, bias, out);
}

// round 7
// speedup vs baseline: 1.1419x; 1.1419x over previous
#include <cuda_runtime.h>
#include <cstddef>

// Problem constants
#define BATCH   16
#define IN_CH   2
#define FDIM    2048
#define TDIM    1024
#define NBANDS  64
#define BANDSZ  32      // FDIM / NBANDS
#define EMB     128

#define T_CHUNK 256
#define THREADS 256

__global__ __launch_bounds__(THREADS)
void bandsplit_kernel(const float* __restrict__ x,
                      const float* __restrict__ W,
                      const float* __restrict__ bias,
                      float* __restrict__ out)
{
    // Per-block means (written warp-locally, read warp-locally): 2 KB
    __shared__ float xm0[T_CHUNK];
    __shared__ float xm1[T_CHUNK];

    const int g  = blockIdx.x;
    const int tc = g & 3;               // t-chunk index (TDIM / T_CHUNK = 4)
    const int n  = (g >> 2) & 63;       // band
    const int b  = g >> 8;              // batch

    const int tid  = threadIdx.x;
    const int lane = tid & 31;
    const int wrp  = tid >> 5;          // 0..7 ; warp owns 32 consecutive t

    const int fg = lane >> 3;           // f-group (4 x 8 rows)
    const int c8 = lane & 7;            // float4 column within warp's 32 t
    const int t_warp = tc * T_CHUNK + wrp * 32;

    // ---------------- Phase 1: warp-local band sum (16 float4 loads) --------
    // x index: ((b*IN_CH + c)*FDIM + f)*TDIM + t
    const size_t ft   = (size_t)FDIM * TDIM;
    const int    row4 = TDIM / 4;

    const float4* xp0 = (const float4*)(x + (size_t)b * IN_CH * ft
                                          + (size_t)(n * BANDSZ + fg * 8) * TDIM
                                          + t_warp) + c8;
    const float4* xp1 = xp0 + ft / 4;

    float a0[4] = {0.f, 0.f, 0.f, 0.f};
    float a1[4] = {0.f, 0.f, 0.f, 0.f};
    #pragma unroll
    for (int f = 0; f < 8; f++) {
        const float4 v = __ldcs(xp0 + (size_t)f * row4);
        a0[0] += v.x; a0[1] += v.y; a0[2] += v.z; a0[3] += v.w;
    }
    #pragma unroll
    for (int f = 0; f < 8; f++) {
        const float4 v = __ldcs(xp1 + (size_t)f * row4);
        a1[0] += v.x; a1[1] += v.y; a1[2] += v.z; a1[3] += v.w;
    }

    // Cross-f butterfly: lanes {l, l^8, l^16, l^24} share the same c8 column.
    #pragma unroll
    for (int k = 0; k < 4; k++) {
        a0[k] += __shfl_xor_sync(0xffffffffu, a0[k], 8);
        a0[k] += __shfl_xor_sync(0xffffffffu, a0[k], 16);
        a1[k] += __shfl_xor_sync(0xffffffffu, a1[k], 8);
        a1[k] += __shfl_xor_sync(0xffffffffu, a1[k], 16);
    }

    // fg==0 lanes publish the warp's 32 means (scaled) to smem. No block sync.
    if (fg == 0) {
        const float inv = 1.f / BANDSZ;
        float4 m0, m1;
        m0.x = a0[0] * inv; m0.y = a0[1] * inv; m0.z = a0[2] * inv; m0.w = a0[3] * inv;
        m1.x = a1[0] * inv; m1.y = a1[1] * inv; m1.z = a1[2] * inv; m1.w = a1[3] * inv;
        ((float4*)(xm0 + wrp * 32))[c8] = m0;
        ((float4*)(xm1 + wrp * 32))[c8] = m1;
    }

    // Weights (independent of smem above).
    const int e4 = lane * 4;            // 32 lanes x 4 = full EMB row
    const float4 w0 = *(const float4*)(W + ((size_t)n * IN_CH + 0) * EMB + e4);
    const float4 w1 = *(const float4*)(W + ((size_t)n * IN_CH + 1) * EMB + e4);
    const float4 bb = *(const float4*)(bias + (size_t)n * EMB + e4);

    __syncwarp();

    // ---------------- Phase 2: warp writes its own 32-t span ----------------
    // out index: ((b*NBANDS + n)*TDIM + t)*EMB + e
    float4* op = (float4*)(out + (((size_t)b * NBANDS + n) * TDIM + t_warp) * EMB + e4);
    const float* pm0 = xm0 + wrp * 32;
    const float* pm1 = xm1 + wrp * 32;

    #pragma unroll 8
    for (int t = 0; t < 32; t++) {
        const float m0 = pm0[t];        // warp-uniform smem broadcast
        const float m1 = pm1[t];
        float4 r;
        r.x = fmaf(m0, w0.x, fmaf(m1, w1.x, bb.x));
        r.y = fmaf(m0, w0.y, fmaf(m1, w1.y, bb.y));
        r.z = fmaf(m0, w0.z, fmaf(m1, w1.z, bb.z));
        r.w = fmaf(m0, w0.w, fmaf(m1, w1.w, bb.w));
        __stcs(op + (size_t)t * (EMB / 4), r);
    }
}

extern "C" void kernel_launch(void* const* d_in, const int* in_sizes, int n_in,
                              void* d_out, int out_size)
{
    const float* x    = (const float*)d_in[0];
    const float* W    = (const float*)d_in[1];
    const float* bias = (const float*)d_in[2];
    float* out        = (float*)d_out;

    const int grid = BATCH * NBANDS * (TDIM / T_CHUNK);  // 4096
    bandsplit_kernel<<<grid, THREADS>>>(x, W, bias, out);
}